// round 12
// baseline (speedup 1.0000x reference)
#include <cuda_runtime.h>
#include <math.h>
#include <stdint.h>

#define H 450
#define B 1024
#define NE 30
#define NH 16384      // node rows  (B*16)
#define ER 30720      // edge rows  (B*30)
#define SR 31744      // stop rows  (B*31)
#define V 780

// ---------------- static tree tables ----------------
__constant__ int c_src[30] = {0,1, 0,2, 1,3, 1,4, 2,5, 2,6, 3,7, 3,8, 4,9, 4,10, 5,11, 5,12, 6,13, 6,14, 7,15};
// DFS-time EFFECTIVE predecessors: only preds already computed at the edge's
// DFS position (preds not yet visited contribute zero in the reference).
__constant__ int c_pred0[30] = {-1,5,1,9,0,13,0,17,2,21,2,25,4,29,4,-1,6,-1,6,-1,8,-1,8,-1,10,-1,10,-1,12,-1};
__constant__ int c_pred1[30] = {-1,7,-1,11,-1,15,5,19,-1,23,9,27,-1,-1,13,-1,-1,-1,17,-1,-1,-1,21,-1,-1,-1,25,-1,-1,-1};
// [0..29]  level-ordered edge list (7 levels: 9,5,4,3,3,2,4 edges)
// [30..50] edges needing hU (per level, 21 total)
// [51..66] pred-entry -> edge map (entry0 = zero row)
__constant__ int c_maps[67] = {
  0,15,17,19,21,23,25,27,29,  4,7,9,11,13,  3,5,12,14,  1,6,28,  2,16,18,  8,10,  20,22,24,26,
  0,15,17,19,21,23,25,27,29,  4,7,9,11,13,  5,12,  1,6,  2,  8,10,
  -1,0,2,4,6,8,10,12,14,16,18,20,22,24,26,28
};

// ---------------- scratch pool (no allocations allowed) ----------------
constexpr size_t SZ_NODE = (size_t)NH * H;
constexpr size_t SZ_EDGE = (size_t)ER * H;
constexpr size_t SZ_LVL  = (size_t)9216 * H;   // max level = 9 edges
constexpr size_t SZ_STOP = (size_t)SR * H;
constexpr size_t OFF_X    = 0;
constexpr size_t OFF_XR   = OFF_X   + SZ_NODE;
constexpr size_t OFF_XZ   = OFF_XR  + SZ_NODE;
constexpr size_t OFF_XH   = OFF_XZ  + SZ_NODE;
constexpr size_t OFF_XU   = OFF_XH  + SZ_NODE;
constexpr size_t OFF_H    = OFF_XU  + SZ_NODE;
constexpr size_t OFF_HU   = OFF_H   + SZ_EDGE;
constexpr size_t OFF_SUMH = OFF_HU  + SZ_EDGE;
constexpr size_t OFF_SHC  = OFF_SUMH+ SZ_EDGE;
constexpr size_t OFF_SGC  = OFF_SHC + SZ_LVL;
constexpr size_t OFF_TZ   = OFF_SGC + SZ_LVL;
constexpr size_t OFF_O    = OFF_TZ  + SZ_LVL;
constexpr size_t OFF_HS   = OFF_O   + SZ_STOP;
constexpr size_t OFF_TVU  = OFF_HS  + SZ_STOP;
constexpr size_t OFF_TVW  = OFF_TVU + (size_t)B*H;
constexpr size_t OFF_P    = OFF_TVW + (size_t)B*H;
constexpr size_t OFF_SCO  = OFF_P   + SZ_NODE;
constexpr size_t OFF_PL   = OFF_SCO + (size_t)NH*V;
constexpr size_t OFF_PC   = OFF_PL  + NH;
constexpr size_t OFF_SL   = OFF_PC  + NH;
constexpr size_t OFF_SCR  = OFF_SL  + SR;
constexpr size_t POOL_SZ  = OFF_SCR + SR;
__device__ float g_pool[POOL_SZ];

// ---------------- generic GEMM: C = A @ W^T, fp32 accumulation ----------------
// 128x128 block tile, 8x8 per-thread tile, float4 LDS, register-staged
// prefetch + DOUBLE-BUFFERED smem (one __syncthreads per K-tile).
// A: [M,K] row-major (optionally row-gathered per 1024-row block via c_maps)
// W: [N,K] row-major with leading dim ldw (supports column-sliced weights)
// NOTE: K must be even (450 / 56 here) — float2 staging relies on it.
#define BM 128
#define BN 128
#define BK 16

enum { EPI_STORE = 0, EPI_CELL = 1, EPI_STOP = 2, EPI_PRED = 3 };

struct GemmArgs {
  int M, N, K;
  const float* A; int lda;
  int amap_off;             // -1: none; else c_maps base, edge = c_maps[off + (row>>10)]
  const float* W; int ldw;
  const float* bias;        // EPI_STORE only (nullable)
  float* C; int ldc;
  int epi;
  int out_map;              // EPI_STORE: remap out row via amap (hU)
  int emap_off;             // EPI_CELL: epilogue edge map
  // CELL aux
  const float* Tz; const float* XZ; const float* XH;
  const float* Wzb; const float* Whb; const float* SumH; float* Hout;
  // STOP aux
  const float* XU; const float* TVu;
  // PRED aux
  const float* TVw;
};

__device__ __forceinline__ float sigmoidf_(float x) { return 1.f / (1.f + expf(-x)); }

__global__ __launch_bounds__(256, 2) void gemm_kernel(GemmArgs a) {
  __shared__ __align__(16) float As[2][BK][BM + 4];
  __shared__ __align__(16) float Bs[2][BK][BN + 4];
  const int tn0 = blockIdx.x * BN;
  const int tm0 = blockIdx.y * BM;
  const int tid = threadIdx.x;
  const int tx = tid & 15, ty = tid >> 4;

  int eblk = -2;
  if (a.amap_off >= 0) eblk = c_maps[a.amap_off + (tm0 >> 10)];

  float acc[8][8];
  #pragma unroll
  for (int i = 0; i < 8; i++)
    #pragma unroll
    for (int j = 0; j < 8; j++) acc[i][j] = 0.f;

  const int lr = tid >> 1;          // load row within tile (0..127)
  const int lk = (tid & 1) * 8;     // k base (0 or 8)
  const float* Arow = nullptr;
  if (eblk != -1) {
    int grow = (a.amap_off >= 0) ? (eblk * 1024 + ((tm0 + lr) & 1023)) : (tm0 + lr);
    Arow = a.A + (size_t)grow * a.lda;
  }
  const bool nok = (tn0 + lr) < a.N;
  const float* Wrow = a.W + (size_t)(tn0 + lr) * a.ldw;

  const int K = a.K;
  const int T = (K + BK - 1) / BK;
  float2 ar[4], br[4];
  // stage + store tile 0 into buffer 0
  #pragma unroll
  for (int j = 0; j < 4; j++) {
    int k = lk + 2 * j;
    ar[j] = (Arow && k + 2 <= K) ? *(const float2*)(Arow + k) : make_float2(0.f, 0.f);
    br[j] = (nok  && k + 2 <= K) ? *(const float2*)(Wrow + k) : make_float2(0.f, 0.f);
  }
  #pragma unroll
  for (int j = 0; j < 4; j++) {
    As[0][lk + 2 * j][lr]     = ar[j].x;
    As[0][lk + 2 * j + 1][lr] = ar[j].y;
    Bs[0][lk + 2 * j][lr]     = br[j].x;
    Bs[0][lk + 2 * j + 1][lr] = br[j].y;
  }
  __syncthreads();

  for (int t = 0; t < T; t++) {
    // issue next tile's global loads (overlap with compute below)
    if (t + 1 < T) {
      int kn = (t + 1) * BK;
      #pragma unroll
      for (int j = 0; j < 4; j++) {
        int k = kn + lk + 2 * j;
        ar[j] = (Arow && k + 2 <= K) ? *(const float2*)(Arow + k) : make_float2(0.f, 0.f);
        br[j] = (nok  && k + 2 <= K) ? *(const float2*)(Wrow + k) : make_float2(0.f, 0.f);
      }
    }
    const int cur = t & 1;
    #pragma unroll
    for (int k = 0; k < BK; k++) {
      float4 a0 = *(const float4*)&As[cur][k][ty * 4];
      float4 a1 = *(const float4*)&As[cur][k][64 + ty * 4];
      float4 b0 = *(const float4*)&Bs[cur][k][tx * 4];
      float4 b1 = *(const float4*)&Bs[cur][k][64 + tx * 4];
      float af[8] = {a0.x, a0.y, a0.z, a0.w, a1.x, a1.y, a1.z, a1.w};
      float bf[8] = {b0.x, b0.y, b0.z, b0.w, b1.x, b1.y, b1.z, b1.w};
      #pragma unroll
      for (int i = 0; i < 8; i++)
        #pragma unroll
        for (int j = 0; j < 8; j++) acc[i][j] = fmaf(af[i], bf[j], acc[i][j]);
    }
    if (t + 1 < T) {
      const int nxt = (t + 1) & 1;
      #pragma unroll
      for (int j = 0; j < 4; j++) {
        As[nxt][lk + 2 * j][lr]     = ar[j].x;
        As[nxt][lk + 2 * j + 1][lr] = ar[j].y;
        Bs[nxt][lk + 2 * j][lr]     = br[j].x;
        Bs[nxt][lk + 2 * j + 1][lr] = br[j].y;
      }
      __syncthreads();
    }
  }

  #pragma unroll
  for (int i = 0; i < 8; i++) {
    int r = tm0 + ((i < 4) ? (ty * 4 + i) : (64 + ty * 4 + i - 4));
    if (r >= a.M) continue;
    int b = r & 1023;
    #pragma unroll
    for (int j = 0; j < 8; j++) {
      int n = tn0 + ((j < 4) ? (tx * 4 + j) : (64 + tx * 4 + j - 4));
      if (n >= a.N) continue;
      float v = acc[i][j];
      if (a.epi == EPI_STORE) {
        if (a.bias) v += a.bias[n];
        int row = r;
        if (a.out_map) row = eblk * 1024 + b;
        a.C[(size_t)row * a.ldc + n] = v;
      } else if (a.epi == EPI_CELL) {
        int e = c_maps[a.emap_off + (r >> 10)];
        int g = e * 1024 + b;
        int xr = (b * 16 + c_src[e]) * H;
        float z   = sigmoidf_(a.Tz[(size_t)r * H + n] + a.XZ[xr + n] + a.Wzb[n]);
        float pre = tanhf(v + a.XH[xr + n] + a.Whb[n]);
        float sh  = a.SumH[(size_t)g * H + n];
        a.Hout[(size_t)g * H + n] = (1.f - z) * sh + z * pre;
      } else if (a.epi == EPI_STOP) {
        int e = r >> 10;                       // 0..30 (30 == root rows)
        int srcn = (e < 30) ? c_src[e] : 0;
        int xr = (b * 16 + srcn) * H;
        float t = v + a.XU[xr + n] + a.TVu[(size_t)b * H + n];
        a.C[(size_t)r * a.ldc + n] = fmaxf(t, 0.f);
      } else { // EPI_PRED
        float t = v + a.TVw[(size_t)b * H + n];
        a.C[(size_t)r * a.ldc + n] = fmaxf(t, 0.f);
      }
    }
  }
}

// ---------------- elementwise / reduce kernels ----------------
__global__ void embed_kernel(float* X, const int* wid, const float* emb) {
  int n = blockIdx.x;
  const float* src = emb + (size_t)wid[n] * H;
  float* dst = X + (size_t)n * H;
  for (int j = threadIdx.x; j < H; j += blockDim.x) dst[j] = src[j];
}

__global__ void gather_cell_kernel(int lvl_off, const float* __restrict__ Urb,
                                   const float* __restrict__ XR,
                                   const float* __restrict__ h,
                                   const float* __restrict__ hU,
                                   float* SumH, float* SHc, float* SGc) {
  int r = blockIdx.x;
  int idx = r >> 10, b = r & 1023;
  int e = c_maps[lvl_off + idx];
  int p0 = c_pred0[e], p1 = c_pred1[e];
  const float* xr = XR + (size_t)(b * 16 + c_src[e]) * H;
  size_t go = (size_t)(e * 1024 + b) * H;
  size_t ro = (size_t)r * H;
  for (int j = threadIdx.x; j < H; j += blockDim.x) {
    float sh = 0.f, sg = 0.f;
    if (p0 >= 0) {
      size_t q = (size_t)(p0 * 1024 + b) * H + j;
      float hv = h[q];
      float rr = sigmoidf_(xr[j] + hU[q] + Urb[j]);
      sh += hv; sg += rr * hv;
    }
    if (p1 >= 0) {
      size_t q = (size_t)(p1 * 1024 + b) * H + j;
      float hv = h[q];
      float rr = sigmoidf_(xr[j] + hU[q] + Urb[j]);
      sh += hv; sg += rr * hv;
    }
    SumH[go + j] = sh;
    SHc[ro + j] = sh;
    SGc[ro + j] = sg;
  }
}

__global__ void build_o_kernel(const float* __restrict__ SumH,
                               const float* __restrict__ h, float* O) {
  int r = blockIdx.x;
  size_t off = (size_t)r * H;
  if (r < ER) {
    int e = r >> 10, b = r & 1023;
    if (e & 1) {
      size_t rev = (size_t)((e ^ 1) * 1024 + b) * H;
      for (int j = threadIdx.x; j < H; j += blockDim.x) O[off + j] = SumH[off + j] + h[rev + j];
    } else {
      for (int j = threadIdx.x; j < H; j += blockDim.x) O[off + j] = SumH[off + j];
    }
  } else {
    int b = r - ER;
    size_t r1 = (size_t)(1 * 1024 + b) * H, r3 = (size_t)(3 * 1024 + b) * H;
    for (int j = threadIdx.x; j < H; j += blockDim.x) O[off + j] = h[r1 + j] + h[r3 + j];
  }
}

__global__ void stop_reduce_kernel(const float* __restrict__ Hs,
                                   const float* __restrict__ Usw, const float* __restrict__ Usb,
                                   float* SL, float* SC) {
  __shared__ double red[256];
  int r = blockIdx.x;
  const float* hs = Hs + (size_t)r * H;
  double p = 0.0;
  for (int j = threadIdx.x; j < H; j += 256) p = fma((double)hs[j], (double)Usw[j], p);
  red[threadIdx.x] = p; __syncthreads();
  for (int s = 128; s > 0; s >>= 1) {
    if (threadIdx.x < s) red[threadIdx.x] += red[threadIdx.x + s];
    __syncthreads();
  }
  if (threadIdx.x == 0) {
    double s = red[0] + (double)Usb[0];
    double st = (r < ER) ? (((r >> 10) & 1) ? 0.0 : 1.0) : 0.0;
    double sp = (s > 0.0 ? s : 0.0) + log1p(exp(-fabs(s)));
    SL[r] = (float)(sp - s * st);
    double pr = (s >= 0.0) ? 1.0 : 0.0;
    SC[r] = (pr == st) ? 1.f : 0.f;
  }
}

__global__ void pred_ce_kernel(const float* __restrict__ scores, const int* __restrict__ wid,
                               float* PL, float* PC) {
  __shared__ float smax[256]; __shared__ int sidx[256]; __shared__ double ssum[256];
  int r = blockIdx.x;
  const float* sc = scores + (size_t)r * V;
  float m = -1e30f; int mi = 0x7fffffff;
  for (int v = threadIdx.x; v < V; v += 256) {
    float x = sc[v];
    if (x > m) { m = x; mi = v; }
  }
  smax[threadIdx.x] = m; sidx[threadIdx.x] = mi; __syncthreads();
  for (int s = 128; s > 0; s >>= 1) {
    if (threadIdx.x < s) {
      float om = smax[threadIdx.x + s]; int oi = sidx[threadIdx.x + s];
      if (om > smax[threadIdx.x] || (om == smax[threadIdx.x] && oi < sidx[threadIdx.x])) {
        smax[threadIdx.x] = om; sidx[threadIdx.x] = oi;
      }
    }
    __syncthreads();
  }
  float mx = smax[0]; int amax = sidx[0];
  double p = 0.0;
  for (int v = threadIdx.x; v < V; v += 256) p += (double)expf(sc[v] - mx);
  ssum[threadIdx.x] = p; __syncthreads();
  for (int s = 128; s > 0; s >>= 1) {
    if (threadIdx.x < s) ssum[threadIdx.x] += ssum[threadIdx.x + s];
    __syncthreads();
  }
  if (threadIdx.x == 0) {
    double lse = (double)mx + log(ssum[0]);
    int k = r >> 10, b = r & 1023;
    int t = wid[b * 16 + k];       // entry k targets node k (entry0 -> root)
    PL[r] = (float)(lse - (double)sc[t]);
    PC[r] = (amax == t) ? 1.f : 0.f;
  }
}

__global__ void finalize_kernel(const float* PL, const float* PC,
                                const float* SL, const float* SC,
                                float* out, int out_size) {
  __shared__ double s0[256], s1[256], s2[256], s3[256];
  int tid = threadIdx.x;
  double pl = 0, pc = 0, sl = 0, sc = 0;
  for (int r = tid; r < NH; r += 256) { pl += PL[r]; pc += PC[r]; }
  for (int r = tid; r < SR; r += 256) { sl += SL[r]; sc += SC[r]; }
  s0[tid] = pl; s1[tid] = sl; s2[tid] = pc; s3[tid] = sc;
  __syncthreads();
  for (int s = 128; s > 0; s >>= 1) {
    if (tid < s) { s0[tid] += s0[tid + s]; s1[tid] += s1[tid + s]; s2[tid] += s2[tid + s]; s3[tid] += s3[tid + s]; }
    __syncthreads();
  }
  if (tid == 0) {
    float vals[4] = { (float)(s0[0] / 1024.0), (float)(s1[0] / 1024.0),
                      (float)(s2[0] / 16384.0), (float)(s3[0] / 31744.0) };
    for (int i = 0; i < 4 && i < out_size; i++) out[i] = vals[i];
  }
}

// ---------------- host orchestration ----------------
static GemmArgs mk(int M, int N, int K, const float* A, int lda, int amap,
                   const float* W, int ldw, const float* bias,
                   float* C, int ldc, int epi, int omap, int emap) {
  GemmArgs a = {};
  a.M = M; a.N = N; a.K = K; a.A = A; a.lda = lda; a.amap_off = amap;
  a.W = W; a.ldw = ldw; a.bias = bias; a.C = C; a.ldc = ldc;
  a.epi = epi; a.out_map = omap; a.emap_off = emap;
  return a;
}
static void run(const GemmArgs& a) {
  dim3 grid((a.N + BN - 1) / BN, (a.M + BM - 1) / BM);
  gemm_kernel<<<grid, 256>>>(a);
}

extern "C" void kernel_launch(void* const* d_in, const int* in_sizes, int n_in,
                              void* d_out, int out_size) {
  const int*   wid      = (const int*)  d_in[0];
  const float* tree_vec = (const float*)d_in[1];
  const float* emb      = (const float*)d_in[2];
  const float* W_r      = (const float*)d_in[3];
  const float* U_r_w    = (const float*)d_in[4];
  const float* U_r_b    = (const float*)d_in[5];
  const float* W_z_w    = (const float*)d_in[6];
  const float* W_z_b    = (const float*)d_in[7];
  const float* W_h_w    = (const float*)d_in[8];
  const float* W_h_b    = (const float*)d_in[9];
  const float* W_w      = (const float*)d_in[10];
  const float* W_b      = (const float*)d_in[11];
  const float* U_w      = (const float*)d_in[12];
  const float* U_b      = (const float*)d_in[13];
  const float* W_o_w    = (const float*)d_in[14];
  const float* W_o_b    = (const float*)d_in[15];
  const float* U_s_w    = (const float*)d_in[16];
  const float* U_s_b    = (const float*)d_in[17];

  float* pool = nullptr;
  cudaGetSymbolAddress((void**)&pool, g_pool);
  float* X    = pool + OFF_X;
  float* XR   = pool + OFF_XR;
  float* XZ   = pool + OFF_XZ;
  float* XH   = pool + OFF_XH;
  float* XU   = pool + OFF_XU;
  float* h    = pool + OFF_H;
  float* hU   = pool + OFF_HU;
  float* SumH = pool + OFF_SUMH;
  float* SHc  = pool + OFF_SHC;
  float* SGc  = pool + OFF_SGC;
  float* Tz   = pool + OFF_TZ;
  float* O    = pool + OFF_O;
  float* Hs   = pool + OFF_HS;
  float* TVu  = pool + OFF_TVU;
  float* TVw  = pool + OFF_TVW;
  float* P    = pool + OFF_P;
  float* SCO  = pool + OFF_SCO;
  float* PL   = pool + OFF_PL;
  float* PC   = pool + OFF_PC;
  float* SL   = pool + OFF_SL;
  float* SCR  = pool + OFF_SCR;

  // 1) node embeddings + per-node precomputes
  embed_kernel<<<NH, 256>>>(X, wid, emb);
  run(mk(NH, H, H, X, H, -1, W_r,   H,     nullptr, XR, H, EPI_STORE, 0, -1));
  run(mk(NH, H, H, X, H, -1, W_z_w, 2 * H, nullptr, XZ, H, EPI_STORE, 0, -1));   // W_z cols [0,H)
  run(mk(NH, H, H, X, H, -1, W_h_w, 2 * H, nullptr, XH, H, EPI_STORE, 0, -1));   // W_h cols [0,H)
  run(mk(NH, H, H, X, H, -1, U_w,   956,   nullptr, XU, H, EPI_STORE, 0, -1));   // U_w cols [0,H)
  // per-tree tree_vec projections (+bias folded in)
  run(mk(B, H, 56, tree_vec, 56, -1, U_w + 2 * H, 956, U_b, TVu, H, EPI_STORE, 0, -1)); // U_w cols [2H,2H+56)
  run(mk(B, H, 56, tree_vec, 56, -1, W_w + H,     506, W_b, TVw, H, EPI_STORE, 0, -1)); // W_w cols [H,H+56)

  // 2) 7-level recurrence over the DFS-time dependency DAG
  const int LVL_OFF[8] = {0, 9, 14, 18, 21, 24, 26, 30};
  const int HUL_OFF[8] = {0, 9, 14, 16, 18, 19, 21, 21};
  for (int l = 0; l < 7; l++) {
    int ne = LVL_OFF[l + 1] - LVL_OFF[l];
    int rows = ne * 1024;
    gather_cell_kernel<<<rows, 256>>>(LVL_OFF[l], U_r_b, XR, h, hU, SumH, SHc, SGc);
    // Tz = sum_h @ W_z_h^T
    run(mk(rows, H, H, SHc, H, -1, W_z_w + H, 2 * H, nullptr, Tz, H, EPI_STORE, 0, -1));
    // pre/z/new_h fused epilogue on (sum_g @ W_h_h^T)
    GemmArgs a2 = mk(rows, H, H, SGc, H, -1, W_h_w + H, 2 * H, nullptr, nullptr, 0,
                     EPI_CELL, 0, LVL_OFF[l]);
    a2.Tz = Tz; a2.XZ = XZ; a2.XH = XH; a2.Wzb = W_z_b; a2.Whb = W_h_b;
    a2.SumH = SumH; a2.Hout = h;
    run(a2);
    // hU for edges consumed later
    int nhu = HUL_OFF[l + 1] - HUL_OFF[l];
    if (nhu > 0)
      run(mk(nhu * 1024, H, H, h, H, 30 + HUL_OFF[l], U_r_w, H, nullptr, hU, H, EPI_STORE, 1, -1));
  }

  // 3) stop head
  build_o_kernel<<<SR, 256>>>(SumH, h, O);
  GemmArgs as = mk(SR, H, H, O, H, -1, U_w + H, 956, nullptr, Hs, H, EPI_STOP, 0, -1);
  as.XU = XU; as.TVu = TVu;
  run(as);
  stop_reduce_kernel<<<SR, 256>>>(Hs, U_s_w, U_s_b, SL, SCR);

  // 4) word-prediction head
  GemmArgs ap = mk(NH, H, H, h, H, 51, W_w, 506, nullptr, P, H, EPI_PRED, 0, -1);
  ap.TVw = TVw;
  run(ap);
  run(mk(NH, V, H, P, H, -1, W_o_w, H, W_o_b, SCO, V, EPI_STORE, 0, -1));
  pred_ce_kernel<<<NH, 256>>>(SCO, wid, PL, PC);

  // 5) deterministic final reduction
  finalize_kernel<<<1, 256>>>(PL, PC, SL, SCR, (float*)d_out, out_size);
}

// round 13
// speedup vs baseline: 1.1168x; 1.1168x over previous
#include <cuda_runtime.h>
#include <math.h>
#include <stdint.h>

#define H 450
#define B 1024
#define NE 30
#define NH 16384      // node rows  (B*16)
#define ER 30720      // edge rows  (B*30)
#define SR 31744      // stop rows  (B*31)
#define V 780

// ---------------- static tree tables ----------------
__constant__ int c_src[30] = {0,1, 0,2, 1,3, 1,4, 2,5, 2,6, 3,7, 3,8, 4,9, 4,10, 5,11, 5,12, 6,13, 6,14, 7,15};
// DFS-time EFFECTIVE predecessors: only preds already computed at the edge's
// DFS position (preds not yet visited contribute zero in the reference).
__constant__ int c_pred0[30] = {-1,5,1,9,0,13,0,17,2,21,2,25,4,29,4,-1,6,-1,6,-1,8,-1,8,-1,10,-1,10,-1,12,-1};
__constant__ int c_pred1[30] = {-1,7,-1,11,-1,15,5,19,-1,23,9,27,-1,-1,13,-1,-1,-1,17,-1,-1,-1,21,-1,-1,-1,25,-1,-1,-1};
// [0..29]  level-ordered edge list (7 levels: 9,5,4,3,3,2,4 edges)
// [30..50] edges needing hU (per level, 21 total)
// [51..66] pred-entry -> edge map (entry0 = zero row)
__constant__ int c_maps[67] = {
  0,15,17,19,21,23,25,27,29,  4,7,9,11,13,  3,5,12,14,  1,6,28,  2,16,18,  8,10,  20,22,24,26,
  0,15,17,19,21,23,25,27,29,  4,7,9,11,13,  5,12,  1,6,  2,  8,10,
  -1,0,2,4,6,8,10,12,14,16,18,20,22,24,26,28
};

// ---------------- scratch pool (no allocations allowed) ----------------
constexpr size_t SZ_NODE = (size_t)NH * H;
constexpr size_t SZ_EDGE = (size_t)ER * H;
constexpr size_t SZ_LVL  = (size_t)9216 * H;   // max level = 9 edges
constexpr size_t SZ_STOP = (size_t)SR * H;
constexpr size_t OFF_X    = 0;
constexpr size_t OFF_XR   = OFF_X   + SZ_NODE;
constexpr size_t OFF_XZ   = OFF_XR  + SZ_NODE;
constexpr size_t OFF_XH   = OFF_XZ  + SZ_NODE;
constexpr size_t OFF_XU   = OFF_XH  + SZ_NODE;
constexpr size_t OFF_H    = OFF_XU  + SZ_NODE;
constexpr size_t OFF_HU   = OFF_H   + SZ_EDGE;
constexpr size_t OFF_SUMH = OFF_HU  + SZ_EDGE;
constexpr size_t OFF_SHC  = OFF_SUMH+ SZ_EDGE;
constexpr size_t OFF_SGC  = OFF_SHC + SZ_LVL;
constexpr size_t OFF_TZ   = OFF_SGC + SZ_LVL;
constexpr size_t OFF_O    = OFF_TZ  + SZ_LVL;
constexpr size_t OFF_HS   = OFF_O   + SZ_STOP;
constexpr size_t OFF_TVU  = OFF_HS  + SZ_STOP;
constexpr size_t OFF_TVW  = OFF_TVU + (size_t)B*H;
constexpr size_t OFF_P    = OFF_TVW + (size_t)B*H;
constexpr size_t OFF_SCO  = OFF_P   + SZ_NODE;
constexpr size_t OFF_PL   = OFF_SCO + (size_t)NH*V;
constexpr size_t OFF_PC   = OFF_PL  + NH;
constexpr size_t OFF_SL   = OFF_PC  + NH;
constexpr size_t OFF_SCR  = OFF_SL  + SR;
constexpr size_t POOL_SZ  = OFF_SCR + SR;
__device__ float g_pool[POOL_SZ];

// ---------------- generic GEMM: C = A @ W^T, fp32 accumulation ----------------
// 128x64 block tile, 8x4 per-thread tile, float4 LDS, register-staged
// prefetch pipeline (R11 structure), 3 CTAs/SM (24 warps).
// A: [M,K] row-major (optionally row-gathered per 1024-row block via c_maps)
// W: [N,K] row-major with leading dim ldw (supports column-sliced weights)
// NOTE: K must be even (450 / 56 here) — float2 staging relies on it.
#define BM 128
#define BN 64
#define BK 16

enum { EPI_STORE = 0, EPI_CELL = 1, EPI_STOP = 2, EPI_PRED = 3 };

struct GemmArgs {
  int M, N, K;
  const float* A; int lda;
  int amap_off;             // -1: none; else c_maps base, edge = c_maps[off + (row>>10)]
  const float* W; int ldw;
  const float* bias;        // EPI_STORE only (nullable)
  float* C; int ldc;
  int epi;
  int out_map;              // EPI_STORE: remap out row via amap (hU)
  int emap_off;             // EPI_CELL: epilogue edge map
  // CELL aux
  const float* Tz; const float* XZ; const float* XH;
  const float* Wzb; const float* Whb; const float* SumH; float* Hout;
  // STOP aux
  const float* XU; const float* TVu;
  // PRED aux
  const float* TVw;
};

__device__ __forceinline__ float sigmoidf_(float x) { return 1.f / (1.f + expf(-x)); }

__global__ __launch_bounds__(256, 3) void gemm_kernel(GemmArgs a) {
  __shared__ __align__(16) float As[BK][BM + 4];
  __shared__ __align__(16) float Bs[BK][BN + 4];
  const int tn0 = blockIdx.x * BN;
  const int tm0 = blockIdx.y * BM;
  const int tid = threadIdx.x;
  const int tx = tid & 15, ty = tid >> 4;

  int eblk = -2;
  if (a.amap_off >= 0) eblk = c_maps[a.amap_off + (tm0 >> 10)];

  float acc[8][4];
  #pragma unroll
  for (int i = 0; i < 8; i++)
    #pragma unroll
    for (int j = 0; j < 4; j++) acc[i][j] = 0.f;

  // A loader: 2 threads per row, 8 k each (4 float2)
  const int lr = tid >> 1;          // A row within tile (0..127)
  const int lk = (tid & 1) * 8;     // A k base (0 or 8)
  const float* Arow = nullptr;
  if (eblk != -1) {
    int grow = (a.amap_off >= 0) ? (eblk * 1024 + ((tm0 + lr) & 1023)) : (tm0 + lr);
    Arow = a.A + (size_t)grow * a.lda;
  }
  // B loader: 4 threads per row, 4 k each (2 float2)
  const int lb = tid >> 2;          // W row within tile (0..63)
  const int kb = (tid & 3) * 4;     // k base (0,4,8,12)
  const bool nok = (tn0 + lb) < a.N;
  const float* Wrow = a.W + (size_t)(tn0 + lb) * a.ldw;

  const int K = a.K;
  float2 ar[4], br[2];
  // stage first tile
  #pragma unroll
  for (int j = 0; j < 4; j++) {
    int k = lk + 2 * j;
    ar[j] = (Arow && k + 2 <= K) ? *(const float2*)(Arow + k) : make_float2(0.f, 0.f);
  }
  #pragma unroll
  for (int j = 0; j < 2; j++) {
    int k = kb + 2 * j;
    br[j] = (nok && k + 2 <= K) ? *(const float2*)(Wrow + k) : make_float2(0.f, 0.f);
  }

  for (int k0 = 0; k0 < K; k0 += BK) {
    __syncthreads();   // previous tile's readers done
    #pragma unroll
    for (int j = 0; j < 4; j++) {
      As[lk + 2 * j][lr]     = ar[j].x;
      As[lk + 2 * j + 1][lr] = ar[j].y;
    }
    #pragma unroll
    for (int j = 0; j < 2; j++) {
      Bs[kb + 2 * j][lb]     = br[j].x;
      Bs[kb + 2 * j + 1][lb] = br[j].y;
    }
    __syncthreads();
    // issue next tile's global loads (overlap with compute below)
    int kn = k0 + BK;
    if (kn < K) {
      #pragma unroll
      for (int j = 0; j < 4; j++) {
        int k = kn + lk + 2 * j;
        ar[j] = (Arow && k + 2 <= K) ? *(const float2*)(Arow + k) : make_float2(0.f, 0.f);
      }
      #pragma unroll
      for (int j = 0; j < 2; j++) {
        int k = kn + kb + 2 * j;
        br[j] = (nok && k + 2 <= K) ? *(const float2*)(Wrow + k) : make_float2(0.f, 0.f);
      }
    }
    #pragma unroll
    for (int k = 0; k < BK; k++) {
      float4 a0 = *(const float4*)&As[k][ty * 4];
      float4 a1 = *(const float4*)&As[k][64 + ty * 4];
      float4 b0 = *(const float4*)&Bs[k][tx * 4];
      float af[8] = {a0.x, a0.y, a0.z, a0.w, a1.x, a1.y, a1.z, a1.w};
      float bf[4] = {b0.x, b0.y, b0.z, b0.w};
      #pragma unroll
      for (int i = 0; i < 8; i++)
        #pragma unroll
        for (int j = 0; j < 4; j++) acc[i][j] = fmaf(af[i], bf[j], acc[i][j]);
    }
  }

  #pragma unroll
  for (int i = 0; i < 8; i++) {
    int r = tm0 + ((i < 4) ? (ty * 4 + i) : (64 + ty * 4 + i - 4));
    if (r >= a.M) continue;
    int b = r & 1023;
    #pragma unroll
    for (int j = 0; j < 4; j++) {
      int n = tn0 + tx * 4 + j;
      if (n >= a.N) continue;
      float v = acc[i][j];
      if (a.epi == EPI_STORE) {
        if (a.bias) v += a.bias[n];
        int row = r;
        if (a.out_map) row = eblk * 1024 + b;
        a.C[(size_t)row * a.ldc + n] = v;
      } else if (a.epi == EPI_CELL) {
        int e = c_maps[a.emap_off + (r >> 10)];
        int g = e * 1024 + b;
        int xr = (b * 16 + c_src[e]) * H;
        float z   = sigmoidf_(a.Tz[(size_t)r * H + n] + a.XZ[xr + n] + a.Wzb[n]);
        float pre = tanhf(v + a.XH[xr + n] + a.Whb[n]);
        float sh  = a.SumH[(size_t)g * H + n];
        a.Hout[(size_t)g * H + n] = (1.f - z) * sh + z * pre;
      } else if (a.epi == EPI_STOP) {
        int e = r >> 10;                       // 0..30 (30 == root rows)
        int srcn = (e < 30) ? c_src[e] : 0;
        int xr = (b * 16 + srcn) * H;
        float t = v + a.XU[xr + n] + a.TVu[(size_t)b * H + n];
        a.C[(size_t)r * a.ldc + n] = fmaxf(t, 0.f);
      } else { // EPI_PRED
        float t = v + a.TVw[(size_t)b * H + n];
        a.C[(size_t)r * a.ldc + n] = fmaxf(t, 0.f);
      }
    }
  }
}

// ---------------- elementwise / reduce kernels ----------------
__global__ void embed_kernel(float* X, const int* wid, const float* emb) {
  int n = blockIdx.x;
  const float* src = emb + (size_t)wid[n] * H;
  float* dst = X + (size_t)n * H;
  for (int j = threadIdx.x; j < H; j += blockDim.x) dst[j] = src[j];
}

__global__ void gather_cell_kernel(int lvl_off, const float* __restrict__ Urb,
                                   const float* __restrict__ XR,
                                   const float* __restrict__ h,
                                   const float* __restrict__ hU,
                                   float* SumH, float* SHc, float* SGc) {
  int r = blockIdx.x;
  int idx = r >> 10, b = r & 1023;
  int e = c_maps[lvl_off + idx];
  int p0 = c_pred0[e], p1 = c_pred1[e];
  const float* xr = XR + (size_t)(b * 16 + c_src[e]) * H;
  size_t go = (size_t)(e * 1024 + b) * H;
  size_t ro = (size_t)r * H;
  for (int j = threadIdx.x; j < H; j += blockDim.x) {
    float sh = 0.f, sg = 0.f;
    if (p0 >= 0) {
      size_t q = (size_t)(p0 * 1024 + b) * H + j;
      float hv = h[q];
      float rr = sigmoidf_(xr[j] + hU[q] + Urb[j]);
      sh += hv; sg += rr * hv;
    }
    if (p1 >= 0) {
      size_t q = (size_t)(p1 * 1024 + b) * H + j;
      float hv = h[q];
      float rr = sigmoidf_(xr[j] + hU[q] + Urb[j]);
      sh += hv; sg += rr * hv;
    }
    SumH[go + j] = sh;
    SHc[ro + j] = sh;
    SGc[ro + j] = sg;
  }
}

__global__ void build_o_kernel(const float* __restrict__ SumH,
                               const float* __restrict__ h, float* O) {
  int r = blockIdx.x;
  size_t off = (size_t)r * H;
  if (r < ER) {
    int e = r >> 10, b = r & 1023;
    if (e & 1) {
      size_t rev = (size_t)((e ^ 1) * 1024 + b) * H;
      for (int j = threadIdx.x; j < H; j += blockDim.x) O[off + j] = SumH[off + j] + h[rev + j];
    } else {
      for (int j = threadIdx.x; j < H; j += blockDim.x) O[off + j] = SumH[off + j];
    }
  } else {
    int b = r - ER;
    size_t r1 = (size_t)(1 * 1024 + b) * H, r3 = (size_t)(3 * 1024 + b) * H;
    for (int j = threadIdx.x; j < H; j += blockDim.x) O[off + j] = h[r1 + j] + h[r3 + j];
  }
}

__global__ void stop_reduce_kernel(const float* __restrict__ Hs,
                                   const float* __restrict__ Usw, const float* __restrict__ Usb,
                                   float* SL, float* SC) {
  __shared__ double red[256];
  int r = blockIdx.x;
  const float* hs = Hs + (size_t)r * H;
  double p = 0.0;
  for (int j = threadIdx.x; j < H; j += 256) p = fma((double)hs[j], (double)Usw[j], p);
  red[threadIdx.x] = p; __syncthreads();
  for (int s = 128; s > 0; s >>= 1) {
    if (threadIdx.x < s) red[threadIdx.x] += red[threadIdx.x + s];
    __syncthreads();
  }
  if (threadIdx.x == 0) {
    double s = red[0] + (double)Usb[0];
    double st = (r < ER) ? (((r >> 10) & 1) ? 0.0 : 1.0) : 0.0;
    double sp = (s > 0.0 ? s : 0.0) + log1p(exp(-fabs(s)));
    SL[r] = (float)(sp - s * st);
    double pr = (s >= 0.0) ? 1.0 : 0.0;
    SC[r] = (pr == st) ? 1.f : 0.f;
  }
}

__global__ void pred_ce_kernel(const float* __restrict__ scores, const int* __restrict__ wid,
                               float* PL, float* PC) {
  __shared__ float smax[256]; __shared__ int sidx[256]; __shared__ double ssum[256];
  int r = blockIdx.x;
  const float* sc = scores + (size_t)r * V;
  float m = -1e30f; int mi = 0x7fffffff;
  for (int v = threadIdx.x; v < V; v += 256) {
    float x = sc[v];
    if (x > m) { m = x; mi = v; }
  }
  smax[threadIdx.x] = m; sidx[threadIdx.x] = mi; __syncthreads();
  for (int s = 128; s > 0; s >>= 1) {
    if (threadIdx.x < s) {
      float om = smax[threadIdx.x + s]; int oi = sidx[threadIdx.x + s];
      if (om > smax[threadIdx.x] || (om == smax[threadIdx.x] && oi < sidx[threadIdx.x])) {
        smax[threadIdx.x] = om; sidx[threadIdx.x] = oi;
      }
    }
    __syncthreads();
  }
  float mx = smax[0]; int amax = sidx[0];
  double p = 0.0;
  for (int v = threadIdx.x; v < V; v += 256) p += (double)expf(sc[v] - mx);
  ssum[threadIdx.x] = p; __syncthreads();
  for (int s = 128; s > 0; s >>= 1) {
    if (threadIdx.x < s) ssum[threadIdx.x] += ssum[threadIdx.x + s];
    __syncthreads();
  }
  if (threadIdx.x == 0) {
    double lse = (double)mx + log(ssum[0]);
    int k = r >> 10, b = r & 1023;
    int t = wid[b * 16 + k];       // entry k targets node k (entry0 -> root)
    PL[r] = (float)(lse - (double)sc[t]);
    PC[r] = (amax == t) ? 1.f : 0.f;
  }
}

__global__ void finalize_kernel(const float* PL, const float* PC,
                                const float* SL, const float* SC,
                                float* out, int out_size) {
  __shared__ double s0[256], s1[256], s2[256], s3[256];
  int tid = threadIdx.x;
  double pl = 0, pc = 0, sl = 0, sc = 0;
  for (int r = tid; r < NH; r += 256) { pl += PL[r]; pc += PC[r]; }
  for (int r = tid; r < SR; r += 256) { sl += SL[r]; sc += SC[r]; }
  s0[tid] = pl; s1[tid] = sl; s2[tid] = pc; s3[tid] = sc;
  __syncthreads();
  for (int s = 128; s > 0; s >>= 1) {
    if (tid < s) { s0[tid] += s0[tid + s]; s1[tid] += s1[tid + s]; s2[tid] += s2[tid + s]; s3[tid] += s3[tid + s]; }
    __syncthreads();
  }
  if (tid == 0) {
    float vals[4] = { (float)(s0[0] / 1024.0), (float)(s1[0] / 1024.0),
                      (float)(s2[0] / 16384.0), (float)(s3[0] / 31744.0) };
    for (int i = 0; i < 4 && i < out_size; i++) out[i] = vals[i];
  }
}

// ---------------- host orchestration ----------------
static GemmArgs mk(int M, int N, int K, const float* A, int lda, int amap,
                   const float* W, int ldw, const float* bias,
                   float* C, int ldc, int epi, int omap, int emap) {
  GemmArgs a = {};
  a.M = M; a.N = N; a.K = K; a.A = A; a.lda = lda; a.amap_off = amap;
  a.W = W; a.ldw = ldw; a.bias = bias; a.C = C; a.ldc = ldc;
  a.epi = epi; a.out_map = omap; a.emap_off = emap;
  return a;
}
static void run(const GemmArgs& a) {
  dim3 grid((a.N + BN - 1) / BN, (a.M + BM - 1) / BM);
  gemm_kernel<<<grid, 256>>>(a);
}

extern "C" void kernel_launch(void* const* d_in, const int* in_sizes, int n_in,
                              void* d_out, int out_size) {
  const int*   wid      = (const int*)  d_in[0];
  const float* tree_vec = (const float*)d_in[1];
  const float* emb      = (const float*)d_in[2];
  const float* W_r      = (const float*)d_in[3];
  const float* U_r_w    = (const float*)d_in[4];
  const float* U_r_b    = (const float*)d_in[5];
  const float* W_z_w    = (const float*)d_in[6];
  const float* W_z_b    = (const float*)d_in[7];
  const float* W_h_w    = (const float*)d_in[8];
  const float* W_h_b    = (const float*)d_in[9];
  const float* W_w      = (const float*)d_in[10];
  const float* W_b      = (const float*)d_in[11];
  const float* U_w      = (const float*)d_in[12];
  const float* U_b      = (const float*)d_in[13];
  const float* W_o_w    = (const float*)d_in[14];
  const float* W_o_b    = (const float*)d_in[15];
  const float* U_s_w    = (const float*)d_in[16];
  const float* U_s_b    = (const float*)d_in[17];

  float* pool = nullptr;
  cudaGetSymbolAddress((void**)&pool, g_pool);
  float* X    = pool + OFF_X;
  float* XR   = pool + OFF_XR;
  float* XZ   = pool + OFF_XZ;
  float* XH   = pool + OFF_XH;
  float* XU   = pool + OFF_XU;
  float* h    = pool + OFF_H;
  float* hU   = pool + OFF_HU;
  float* SumH = pool + OFF_SUMH;
  float* SHc  = pool + OFF_SHC;
  float* SGc  = pool + OFF_SGC;
  float* Tz   = pool + OFF_TZ;
  float* O    = pool + OFF_O;
  float* Hs   = pool + OFF_HS;
  float* TVu  = pool + OFF_TVU;
  float* TVw  = pool + OFF_TVW;
  float* P    = pool + OFF_P;
  float* SCO  = pool + OFF_SCO;
  float* PL   = pool + OFF_PL;
  float* PC   = pool + OFF_PC;
  float* SL   = pool + OFF_SL;
  float* SCR  = pool + OFF_SCR;

  // 1) node embeddings + per-node precomputes
  embed_kernel<<<NH, 256>>>(X, wid, emb);
  run(mk(NH, H, H, X, H, -1, W_r,   H,     nullptr, XR, H, EPI_STORE, 0, -1));
  run(mk(NH, H, H, X, H, -1, W_z_w, 2 * H, nullptr, XZ, H, EPI_STORE, 0, -1));   // W_z cols [0,H)
  run(mk(NH, H, H, X, H, -1, W_h_w, 2 * H, nullptr, XH, H, EPI_STORE, 0, -1));   // W_h cols [0,H)
  run(mk(NH, H, H, X, H, -1, U_w,   956,   nullptr, XU, H, EPI_STORE, 0, -1));   // U_w cols [0,H)
  // per-tree tree_vec projections (+bias folded in)
  run(mk(B, H, 56, tree_vec, 56, -1, U_w + 2 * H, 956, U_b, TVu, H, EPI_STORE, 0, -1)); // U_w cols [2H,2H+56)
  run(mk(B, H, 56, tree_vec, 56, -1, W_w + H,     506, W_b, TVw, H, EPI_STORE, 0, -1)); // W_w cols [H,H+56)

  // 2) 7-level recurrence over the DFS-time dependency DAG
  const int LVL_OFF[8] = {0, 9, 14, 18, 21, 24, 26, 30};
  const int HUL_OFF[8] = {0, 9, 14, 16, 18, 19, 21, 21};
  for (int l = 0; l < 7; l++) {
    int ne = LVL_OFF[l + 1] - LVL_OFF[l];
    int rows = ne * 1024;
    gather_cell_kernel<<<rows, 256>>>(LVL_OFF[l], U_r_b, XR, h, hU, SumH, SHc, SGc);
    // Tz = sum_h @ W_z_h^T
    run(mk(rows, H, H, SHc, H, -1, W_z_w + H, 2 * H, nullptr, Tz, H, EPI_STORE, 0, -1));
    // pre/z/new_h fused epilogue on (sum_g @ W_h_h^T)
    GemmArgs a2 = mk(rows, H, H, SGc, H, -1, W_h_w + H, 2 * H, nullptr, nullptr, 0,
                     EPI_CELL, 0, LVL_OFF[l]);
    a2.Tz = Tz; a2.XZ = XZ; a2.XH = XH; a2.Wzb = W_z_b; a2.Whb = W_h_b;
    a2.SumH = SumH; a2.Hout = h;
    run(a2);
    // hU for edges consumed later
    int nhu = HUL_OFF[l + 1] - HUL_OFF[l];
    if (nhu > 0)
      run(mk(nhu * 1024, H, H, h, H, 30 + HUL_OFF[l], U_r_w, H, nullptr, hU, H, EPI_STORE, 1, -1));
  }

  // 3) stop head
  build_o_kernel<<<SR, 256>>>(SumH, h, O);
  GemmArgs as = mk(SR, H, H, O, H, -1, U_w + H, 956, nullptr, Hs, H, EPI_STOP, 0, -1);
  as.XU = XU; as.TVu = TVu;
  run(as);
  stop_reduce_kernel<<<SR, 256>>>(Hs, U_s_w, U_s_b, SL, SCR);

  // 4) word-prediction head
  GemmArgs ap = mk(NH, H, H, h, H, 51, W_w, 506, nullptr, P, H, EPI_PRED, 0, -1);
  ap.TVw = TVw;
  run(ap);
  run(mk(NH, V, H, P, H, -1, W_o_w, H, W_o_b, SCO, V, EPI_STORE, 0, -1));
  pred_ce_kernel<<<NH, 256>>>(SCO, wid, PL, PC);

  // 5) deterministic final reduction
  finalize_kernel<<<1, 256>>>(PL, PC, SL, SCR, (float*)d_out, out_size);
}

// round 14
// speedup vs baseline: 1.4651x; 1.3119x over previous
#include <cuda_runtime.h>
#include <math.h>
#include <stdint.h>

#define H 450
#define B 1024
#define NE 30
#define NH 16384      // node rows  (B*16)
#define ER 30720      // edge rows  (B*30)
#define SR 31744      // stop rows  (B*31)
#define V 780

// ---------------- static tree tables ----------------
__constant__ int c_src[30] = {0,1, 0,2, 1,3, 1,4, 2,5, 2,6, 3,7, 3,8, 4,9, 4,10, 5,11, 5,12, 6,13, 6,14, 7,15};
// DFS-time EFFECTIVE predecessors.
__constant__ int c_pred0[30] = {-1,5,1,9,0,13,0,17,2,21,2,25,4,29,4,-1,6,-1,6,-1,8,-1,8,-1,10,-1,10,-1,12,-1};
__constant__ int c_pred1[30] = {-1,7,-1,11,-1,15,5,19,-1,23,9,27,-1,-1,13,-1,-1,-1,17,-1,-1,-1,21,-1,-1,-1,25,-1,-1,-1};
// [0..29] level edge list; [30..50] hU lists; [51..66] pred-entry map
__constant__ int c_maps[67] = {
  0,15,17,19,21,23,25,27,29,  4,7,9,11,13,  3,5,12,14,  1,6,28,  2,16,18,  8,10,  20,22,24,26,
  0,15,17,19,21,23,25,27,29,  4,7,9,11,13,  5,12,  1,6,  2,  8,10,
  -1,0,2,4,6,8,10,12,14,16,18,20,22,24,26,28
};

// ---------------- scratch pool ----------------
constexpr size_t SZ_NODE = (size_t)NH * H;
constexpr size_t SZ_EDGE = (size_t)ER * H;
constexpr size_t SZ_LVL  = (size_t)9216 * H;
constexpr size_t SZ_STOP = (size_t)SR * H;
constexpr size_t OFF_X    = 0;
constexpr size_t OFF_XR   = OFF_X   + SZ_NODE;
constexpr size_t OFF_XZ   = OFF_XR  + SZ_NODE;
constexpr size_t OFF_XH   = OFF_XZ  + SZ_NODE;
constexpr size_t OFF_XU   = OFF_XH  + SZ_NODE;
constexpr size_t OFF_H    = OFF_XU  + SZ_NODE;
constexpr size_t OFF_HU   = OFF_H   + SZ_EDGE;
constexpr size_t OFF_SUMH = OFF_HU  + SZ_EDGE;
constexpr size_t OFF_SHC  = OFF_SUMH+ SZ_EDGE;
constexpr size_t OFF_SGC  = OFF_SHC + SZ_LVL;
constexpr size_t OFF_TZ   = OFF_SGC + SZ_LVL;
constexpr size_t OFF_O    = OFF_TZ  + SZ_LVL;
constexpr size_t OFF_HS   = OFF_O   + SZ_STOP;
constexpr size_t OFF_TVU  = OFF_HS  + SZ_STOP;
constexpr size_t OFF_TVW  = OFF_TVU + (size_t)B*H;
constexpr size_t OFF_P    = OFF_TVW + (size_t)B*H;
constexpr size_t OFF_SCO  = OFF_P   + SZ_NODE;
constexpr size_t OFF_PL   = OFF_SCO + (size_t)NH*V;
constexpr size_t OFF_PC   = OFF_PL  + NH;
constexpr size_t OFF_SL   = OFF_PC  + NH;
constexpr size_t OFF_SCR  = OFF_SL  + SR;
constexpr size_t POOL_SZ  = OFF_SCR + SR;
__device__ float g_pool[POOL_SZ];

// TF32 round (to nearest) — bit pattern returned as float.
__device__ __forceinline__ float tf32r(float x) {
  uint32_t r;
  asm("cvt.rna.tf32.f32 %0, %1;" : "=r"(r) : "f"(x));
  return __uint_as_float(r);
}

// ---------------- GEMM: C = A @ W^T via tf32 tensor cores ----------------
// 128x64 block tile, 8 warps, each warp 32x32 (2 x m16 by 4 x n8 mma tiles).
// Inputs tf32-rounded once at smem store; fp32 accumulation in tensor core.
// M is always a multiple of 128 (all row counts are multiples of 1024).
#define BM 128
#define BN 64
#define BK 16

enum { EPI_STORE = 0, EPI_CELL = 1, EPI_STOP = 2, EPI_PRED = 3 };

struct GemmArgs {
  int M, N, K;
  const float* A; int lda;
  int amap_off;
  const float* W; int ldw;
  const float* bias;
  float* C; int ldc;
  int epi;
  int out_map;
  int emap_off;
  const float* Tz; const float* XZ; const float* XH;
  const float* Wzb; const float* Whb; const float* SumH; float* Hout;
  const float* XU; const float* TVu;
  const float* TVw;
};

__device__ __forceinline__ float sigmoidf_(float x) { return 1.f / (1.f + expf(-x)); }

__device__ __forceinline__ void mma_tf32(float c[4], const uint32_t a[4], const uint32_t b[2]) {
  asm volatile(
    "mma.sync.aligned.m16n8k8.row.col.f32.tf32.tf32.f32 "
    "{%0,%1,%2,%3}, {%4,%5,%6,%7}, {%8,%9}, {%0,%1,%2,%3};"
    : "+f"(c[0]), "+f"(c[1]), "+f"(c[2]), "+f"(c[3])
    : "r"(a[0]), "r"(a[1]), "r"(a[2]), "r"(a[3]), "r"(b[0]), "r"(b[1]));
}

__device__ __forceinline__ void apply_epi(const GemmArgs& a, int eblk, int r, int n, float v) {
  if (n >= a.N || r >= a.M) return;
  int b = r & 1023;
  if (a.epi == EPI_STORE) {
    if (a.bias) v += a.bias[n];
    int row = r;
    if (a.out_map) row = eblk * 1024 + b;
    a.C[(size_t)row * a.ldc + n] = v;
  } else if (a.epi == EPI_CELL) {
    int e = c_maps[a.emap_off + (r >> 10)];
    int g = e * 1024 + b;
    int xr = (b * 16 + c_src[e]) * H;
    float z   = sigmoidf_(a.Tz[(size_t)r * H + n] + a.XZ[xr + n] + a.Wzb[n]);
    float pre = tanhf(v + a.XH[xr + n] + a.Whb[n]);
    float sh  = a.SumH[(size_t)g * H + n];
    a.Hout[(size_t)g * H + n] = (1.f - z) * sh + z * pre;
  } else if (a.epi == EPI_STOP) {
    int e = r >> 10;
    int srcn = (e < 30) ? c_src[e] : 0;
    int xr = (b * 16 + srcn) * H;
    float t = v + a.XU[xr + n] + a.TVu[(size_t)b * H + n];
    a.C[(size_t)r * a.ldc + n] = fmaxf(t, 0.f);
  } else { // EPI_PRED
    float t = v + a.TVw[(size_t)b * H + n];
    a.C[(size_t)r * a.ldc + n] = fmaxf(t, 0.f);
  }
}

__global__ __launch_bounds__(256, 3) void gemm_kernel(GemmArgs a) {
  __shared__ __align__(16) float As[BK][BM + 4];
  __shared__ __align__(16) float Bs[BK][BN + 4];
  const int tn0 = blockIdx.x * BN;
  const int tm0 = blockIdx.y * BM;
  const int tid = threadIdx.x;
  const int wid = tid >> 5, lane = tid & 31;
  const int wm = wid >> 1, wn = wid & 1;      // warp grid 4 x 2
  const int g = lane >> 2, t = lane & 3;

  int eblk = -2;
  if (a.amap_off >= 0) eblk = c_maps[a.amap_off + (tm0 >> 10)];

  float acc[2][4][4];
  #pragma unroll
  for (int mt = 0; mt < 2; mt++)
    #pragma unroll
    for (int nt = 0; nt < 4; nt++)
      #pragma unroll
      for (int e = 0; e < 4; e++) acc[mt][nt][e] = 0.f;

  // A loader: 2 threads per row (0..127), 8 k each
  const int lr = tid >> 1;
  const int lk = (tid & 1) * 8;
  const float* Arow = nullptr;
  if (eblk != -1) {
    int grow = (a.amap_off >= 0) ? (eblk * 1024 + ((tm0 + lr) & 1023)) : (tm0 + lr);
    Arow = a.A + (size_t)grow * a.lda;
  }
  // B loader: 4 threads per row (0..63), 4 k each
  const int lb = tid >> 2;
  const int kb2 = (tid & 3) * 4;
  const bool nok = (tn0 + lb) < a.N;
  const float* Wrow = a.W + (size_t)(tn0 + lb) * a.ldw;

  const int K = a.K;
  float2 ar[4], br[2];
  #pragma unroll
  for (int j = 0; j < 4; j++) {
    int k = lk + 2 * j;
    ar[j] = (Arow && k + 2 <= K) ? *(const float2*)(Arow + k) : make_float2(0.f, 0.f);
  }
  #pragma unroll
  for (int j = 0; j < 2; j++) {
    int k = kb2 + 2 * j;
    br[j] = (nok && k + 2 <= K) ? *(const float2*)(Wrow + k) : make_float2(0.f, 0.f);
  }

  for (int k0 = 0; k0 < K; k0 += BK) {
    __syncthreads();
    #pragma unroll
    for (int j = 0; j < 4; j++) {
      As[lk + 2 * j][lr]     = tf32r(ar[j].x);
      As[lk + 2 * j + 1][lr] = tf32r(ar[j].y);
    }
    #pragma unroll
    for (int j = 0; j < 2; j++) {
      Bs[kb2 + 2 * j][lb]     = tf32r(br[j].x);
      Bs[kb2 + 2 * j + 1][lb] = tf32r(br[j].y);
    }
    __syncthreads();
    int kn = k0 + BK;
    if (kn < K) {
      #pragma unroll
      for (int j = 0; j < 4; j++) {
        int k = kn + lk + 2 * j;
        ar[j] = (Arow && k + 2 <= K) ? *(const float2*)(Arow + k) : make_float2(0.f, 0.f);
      }
      #pragma unroll
      for (int j = 0; j < 2; j++) {
        int k = kn + kb2 + 2 * j;
        br[j] = (nok && k + 2 <= K) ? *(const float2*)(Wrow + k) : make_float2(0.f, 0.f);
      }
    }
    #pragma unroll
    for (int ks = 0; ks < 2; ks++) {
      const int kb = ks * 8;
      uint32_t af[2][4], bf[4][2];
      #pragma unroll
      for (int mt = 0; mt < 2; mt++) {
        int m = wm * 32 + mt * 16;
        af[mt][0] = __float_as_uint(As[kb + t][m + g]);
        af[mt][1] = __float_as_uint(As[kb + t][m + g + 8]);
        af[mt][2] = __float_as_uint(As[kb + t + 4][m + g]);
        af[mt][3] = __float_as_uint(As[kb + t + 4][m + g + 8]);
      }
      #pragma unroll
      for (int nt = 0; nt < 4; nt++) {
        int n = wn * 32 + nt * 8;
        bf[nt][0] = __float_as_uint(Bs[kb + t][n + g]);
        bf[nt][1] = __float_as_uint(Bs[kb + t + 4][n + g]);
      }
      #pragma unroll
      for (int mt = 0; mt < 2; mt++)
        #pragma unroll
        for (int nt = 0; nt < 4; nt++)
          mma_tf32(acc[mt][nt], af[mt], bf[nt]);
    }
  }

  // epilogue: fragment (r,n) mapping — c0:(g,2t) c1:(g,2t+1) c2:(g+8,2t) c3:(g+8,2t+1)
  #pragma unroll
  for (int mt = 0; mt < 2; mt++) {
    int rb = tm0 + wm * 32 + mt * 16;
    #pragma unroll
    for (int nt = 0; nt < 4; nt++) {
      int nb = tn0 + wn * 32 + nt * 8;
      apply_epi(a, eblk, rb + g,     nb + 2 * t,     acc[mt][nt][0]);
      apply_epi(a, eblk, rb + g,     nb + 2 * t + 1, acc[mt][nt][1]);
      apply_epi(a, eblk, rb + g + 8, nb + 2 * t,     acc[mt][nt][2]);
      apply_epi(a, eblk, rb + g + 8, nb + 2 * t + 1, acc[mt][nt][3]);
    }
  }
}

// ---------------- elementwise / reduce kernels ----------------
__global__ void embed_kernel(float* X, const int* wid, const float* emb) {
  int n = blockIdx.x;
  const float* src = emb + (size_t)wid[n] * H;
  float* dst = X + (size_t)n * H;
  for (int j = threadIdx.x; j < H; j += blockDim.x) dst[j] = src[j];
}

__global__ void gather_cell_kernel(int lvl_off, const float* __restrict__ Urb,
                                   const float* __restrict__ XR,
                                   const float* __restrict__ h,
                                   const float* __restrict__ hU,
                                   float* SumH, float* SHc, float* SGc) {
  int r = blockIdx.x;
  int idx = r >> 10, b = r & 1023;
  int e = c_maps[lvl_off + idx];
  int p0 = c_pred0[e], p1 = c_pred1[e];
  const float* xr = XR + (size_t)(b * 16 + c_src[e]) * H;
  size_t go = (size_t)(e * 1024 + b) * H;
  size_t ro = (size_t)r * H;
  for (int j = threadIdx.x; j < H; j += blockDim.x) {
    float sh = 0.f, sg = 0.f;
    if (p0 >= 0) {
      size_t q = (size_t)(p0 * 1024 + b) * H + j;
      float hv = h[q];
      float rr = sigmoidf_(xr[j] + hU[q] + Urb[j]);
      sh += hv; sg += rr * hv;
    }
    if (p1 >= 0) {
      size_t q = (size_t)(p1 * 1024 + b) * H + j;
      float hv = h[q];
      float rr = sigmoidf_(xr[j] + hU[q] + Urb[j]);
      sh += hv; sg += rr * hv;
    }
    SumH[go + j] = sh;
    SHc[ro + j] = sh;
    SGc[ro + j] = sg;
  }
}

__global__ void build_o_kernel(const float* __restrict__ SumH,
                               const float* __restrict__ h, float* O) {
  int r = blockIdx.x;
  size_t off = (size_t)r * H;
  if (r < ER) {
    int e = r >> 10, b = r & 1023;
    if (e & 1) {
      size_t rev = (size_t)((e ^ 1) * 1024 + b) * H;
      for (int j = threadIdx.x; j < H; j += blockDim.x) O[off + j] = SumH[off + j] + h[rev + j];
    } else {
      for (int j = threadIdx.x; j < H; j += blockDim.x) O[off + j] = SumH[off + j];
    }
  } else {
    int b = r - ER;
    size_t r1 = (size_t)(1 * 1024 + b) * H, r3 = (size_t)(3 * 1024 + b) * H;
    for (int j = threadIdx.x; j < H; j += blockDim.x) O[off + j] = h[r1 + j] + h[r3 + j];
  }
}

__global__ void stop_reduce_kernel(const float* __restrict__ Hs,
                                   const float* __restrict__ Usw, const float* __restrict__ Usb,
                                   float* SL, float* SC) {
  __shared__ double red[256];
  int r = blockIdx.x;
  const float* hs = Hs + (size_t)r * H;
  double p = 0.0;
  for (int j = threadIdx.x; j < H; j += 256) p = fma((double)hs[j], (double)Usw[j], p);
  red[threadIdx.x] = p; __syncthreads();
  for (int s = 128; s > 0; s >>= 1) {
    if (threadIdx.x < s) red[threadIdx.x] += red[threadIdx.x + s];
    __syncthreads();
  }
  if (threadIdx.x == 0) {
    double s = red[0] + (double)Usb[0];
    double st = (r < ER) ? (((r >> 10) & 1) ? 0.0 : 1.0) : 0.0;
    double sp = (s > 0.0 ? s : 0.0) + log1p(exp(-fabs(s)));
    SL[r] = (float)(sp - s * st);
    double pr = (s >= 0.0) ? 1.0 : 0.0;
    SC[r] = (pr == st) ? 1.f : 0.f;
  }
}

__global__ void pred_ce_kernel(const float* __restrict__ scores, const int* __restrict__ wid,
                               float* PL, float* PC) {
  __shared__ float smax[256]; __shared__ int sidx[256]; __shared__ double ssum[256];
  int r = blockIdx.x;
  const float* sc = scores + (size_t)r * V;
  float m = -1e30f; int mi = 0x7fffffff;
  for (int v = threadIdx.x; v < V; v += 256) {
    float x = sc[v];
    if (x > m) { m = x; mi = v; }
  }
  smax[threadIdx.x] = m; sidx[threadIdx.x] = mi; __syncthreads();
  for (int s = 128; s > 0; s >>= 1) {
    if (threadIdx.x < s) {
      float om = smax[threadIdx.x + s]; int oi = sidx[threadIdx.x + s];
      if (om > smax[threadIdx.x] || (om == smax[threadIdx.x] && oi < sidx[threadIdx.x])) {
        smax[threadIdx.x] = om; sidx[threadIdx.x] = oi;
      }
    }
    __syncthreads();
  }
  float mx = smax[0]; int amax = sidx[0];
  double p = 0.0;
  for (int v = threadIdx.x; v < V; v += 256) p += (double)expf(sc[v] - mx);
  ssum[threadIdx.x] = p; __syncthreads();
  for (int s = 128; s > 0; s >>= 1) {
    if (threadIdx.x < s) ssum[threadIdx.x] += ssum[threadIdx.x + s];
    __syncthreads();
  }
  if (threadIdx.x == 0) {
    double lse = (double)mx + log(ssum[0]);
    int k = r >> 10, b = r & 1023;
    int t = wid[b * 16 + k];
    PL[r] = (float)(lse - (double)sc[t]);
    PC[r] = (amax == t) ? 1.f : 0.f;
  }
}

__global__ void finalize_kernel(const float* PL, const float* PC,
                                const float* SL, const float* SC,
                                float* out, int out_size) {
  __shared__ double s0[256], s1[256], s2[256], s3[256];
  int tid = threadIdx.x;
  double pl = 0, pc = 0, sl = 0, sc = 0;
  for (int r = tid; r < NH; r += 256) { pl += PL[r]; pc += PC[r]; }
  for (int r = tid; r < SR; r += 256) { sl += SL[r]; sc += SC[r]; }
  s0[tid] = pl; s1[tid] = sl; s2[tid] = pc; s3[tid] = sc;
  __syncthreads();
  for (int s = 128; s > 0; s >>= 1) {
    if (tid < s) { s0[tid] += s0[tid + s]; s1[tid] += s1[tid + s]; s2[tid] += s2[tid + s]; s3[tid] += s3[tid + s]; }
    __syncthreads();
  }
  if (tid == 0) {
    float vals[4] = { (float)(s0[0] / 1024.0), (float)(s1[0] / 1024.0),
                      (float)(s2[0] / 16384.0), (float)(s3[0] / 31744.0) };
    for (int i = 0; i < 4 && i < out_size; i++) out[i] = vals[i];
  }
}

// ---------------- host orchestration ----------------
static GemmArgs mk(int M, int N, int K, const float* A, int lda, int amap,
                   const float* W, int ldw, const float* bias,
                   float* C, int ldc, int epi, int omap, int emap) {
  GemmArgs a = {};
  a.M = M; a.N = N; a.K = K; a.A = A; a.lda = lda; a.amap_off = amap;
  a.W = W; a.ldw = ldw; a.bias = bias; a.C = C; a.ldc = ldc;
  a.epi = epi; a.out_map = omap; a.emap_off = emap;
  return a;
}
static void run(const GemmArgs& a) {
  dim3 grid((a.N + BN - 1) / BN, (a.M + BM - 1) / BM);
  gemm_kernel<<<grid, 256>>>(a);
}

extern "C" void kernel_launch(void* const* d_in, const int* in_sizes, int n_in,
                              void* d_out, int out_size) {
  const int*   wid      = (const int*)  d_in[0];
  const float* tree_vec = (const float*)d_in[1];
  const float* emb      = (const float*)d_in[2];
  const float* W_r      = (const float*)d_in[3];
  const float* U_r_w    = (const float*)d_in[4];
  const float* U_r_b    = (const float*)d_in[5];
  const float* W_z_w    = (const float*)d_in[6];
  const float* W_z_b    = (const float*)d_in[7];
  const float* W_h_w    = (const float*)d_in[8];
  const float* W_h_b    = (const float*)d_in[9];
  const float* W_w      = (const float*)d_in[10];
  const float* W_b      = (const float*)d_in[11];
  const float* U_w      = (const float*)d_in[12];
  const float* U_b      = (const float*)d_in[13];
  const float* W_o_w    = (const float*)d_in[14];
  const float* W_o_b    = (const float*)d_in[15];
  const float* U_s_w    = (const float*)d_in[16];
  const float* U_s_b    = (const float*)d_in[17];

  float* pool = nullptr;
  cudaGetSymbolAddress((void**)&pool, g_pool);
  float* X    = pool + OFF_X;
  float* XR   = pool + OFF_XR;
  float* XZ   = pool + OFF_XZ;
  float* XH   = pool + OFF_XH;
  float* XU   = pool + OFF_XU;
  float* h    = pool + OFF_H;
  float* hU   = pool + OFF_HU;
  float* SumH = pool + OFF_SUMH;
  float* SHc  = pool + OFF_SHC;
  float* SGc  = pool + OFF_SGC;
  float* Tz   = pool + OFF_TZ;
  float* O    = pool + OFF_O;
  float* Hs   = pool + OFF_HS;
  float* TVu  = pool + OFF_TVU;
  float* TVw  = pool + OFF_TVW;
  float* P    = pool + OFF_P;
  float* SCO  = pool + OFF_SCO;
  float* PL   = pool + OFF_PL;
  float* PC   = pool + OFF_PC;
  float* SL   = pool + OFF_SL;
  float* SCR  = pool + OFF_SCR;

  // 1) node embeddings + per-node precomputes
  embed_kernel<<<NH, 256>>>(X, wid, emb);
  run(mk(NH, H, H, X, H, -1, W_r,   H,     nullptr, XR, H, EPI_STORE, 0, -1));
  run(mk(NH, H, H, X, H, -1, W_z_w, 2 * H, nullptr, XZ, H, EPI_STORE, 0, -1));
  run(mk(NH, H, H, X, H, -1, W_h_w, 2 * H, nullptr, XH, H, EPI_STORE, 0, -1));
  run(mk(NH, H, H, X, H, -1, U_w,   956,   nullptr, XU, H, EPI_STORE, 0, -1));
  run(mk(B, H, 56, tree_vec, 56, -1, U_w + 2 * H, 956, U_b, TVu, H, EPI_STORE, 0, -1));
  run(mk(B, H, 56, tree_vec, 56, -1, W_w + H,     506, W_b, TVw, H, EPI_STORE, 0, -1));

  // 2) 7-level recurrence over the DFS-time dependency DAG
  const int LVL_OFF[8] = {0, 9, 14, 18, 21, 24, 26, 30};
  const int HUL_OFF[8] = {0, 9, 14, 16, 18, 19, 21, 21};
  for (int l = 0; l < 7; l++) {
    int ne = LVL_OFF[l + 1] - LVL_OFF[l];
    int rows = ne * 1024;
    gather_cell_kernel<<<rows, 256>>>(LVL_OFF[l], U_r_b, XR, h, hU, SumH, SHc, SGc);
    run(mk(rows, H, H, SHc, H, -1, W_z_w + H, 2 * H, nullptr, Tz, H, EPI_STORE, 0, -1));
    GemmArgs a2 = mk(rows, H, H, SGc, H, -1, W_h_w + H, 2 * H, nullptr, nullptr, 0,
                     EPI_CELL, 0, LVL_OFF[l]);
    a2.Tz = Tz; a2.XZ = XZ; a2.XH = XH; a2.Wzb = W_z_b; a2.Whb = W_h_b;
    a2.SumH = SumH; a2.Hout = h;
    run(a2);
    int nhu = HUL_OFF[l + 1] - HUL_OFF[l];
    if (nhu > 0)
      run(mk(nhu * 1024, H, H, h, H, 30 + HUL_OFF[l], U_r_w, H, nullptr, hU, H, EPI_STORE, 1, -1));
  }

  // 3) stop head
  build_o_kernel<<<SR, 256>>>(SumH, h, O);
  GemmArgs as = mk(SR, H, H, O, H, -1, U_w + H, 956, nullptr, Hs, H, EPI_STOP, 0, -1);
  as.XU = XU; as.TVu = TVu;
  run(as);
  stop_reduce_kernel<<<SR, 256>>>(Hs, U_s_w, U_s_b, SL, SCR);

  // 4) word-prediction head
  GemmArgs ap = mk(NH, H, H, h, H, 51, W_w, 506, nullptr, P, H, EPI_PRED, 0, -1);
  ap.TVw = TVw;
  run(ap);
  run(mk(NH, V, H, P, H, -1, W_o_w, H, W_o_b, SCO, V, EPI_STORE, 0, -1));
  pred_ce_kernel<<<NH, 256>>>(SCO, wid, PL, PC);

  // 5) deterministic final reduction
  finalize_kernel<<<1, 256>>>(PL, PC, SL, SCR, (float*)d_out, out_size);
}

// round 16
// speedup vs baseline: 1.6862x; 1.1510x over previous
#include <cuda_runtime.h>
#include <math.h>
#include <stdint.h>

#define H 450
#define B 1024
#define NE 30
#define NH 16384      // node rows  (B*16)
#define ER 30720      // edge rows  (B*30)
#define SR 31744      // stop rows  (B*31)
#define V 780

// ---------------- static tree tables ----------------
__constant__ int c_src[30] = {0,1, 0,2, 1,3, 1,4, 2,5, 2,6, 3,7, 3,8, 4,9, 4,10, 5,11, 5,12, 6,13, 6,14, 7,15};
// DFS-time EFFECTIVE predecessors.
__constant__ int c_pred0[30] = {-1,5,1,9,0,13,0,17,2,21,2,25,4,29,4,-1,6,-1,6,-1,8,-1,8,-1,10,-1,10,-1,12,-1};
__constant__ int c_pred1[30] = {-1,7,-1,11,-1,15,5,19,-1,23,9,27,-1,-1,13,-1,-1,-1,17,-1,-1,-1,21,-1,-1,-1,25,-1,-1,-1};
// [0..29] level edge list; [30..50] hU lists; [51..66] pred-entry map
__constant__ int c_maps[67] = {
  0,15,17,19,21,23,25,27,29,  4,7,9,11,13,  3,5,12,14,  1,6,28,  2,16,18,  8,10,  20,22,24,26,
  0,15,17,19,21,23,25,27,29,  4,7,9,11,13,  5,12,  1,6,  2,  8,10,
  -1,0,2,4,6,8,10,12,14,16,18,20,22,24,26,28
};

// ---------------- scratch pool ----------------
constexpr size_t SZ_NODE = (size_t)NH * H;
constexpr size_t SZ_EDGE = (size_t)ER * H;
constexpr size_t SZ_LVL  = (size_t)9216 * H;
constexpr size_t SZ_STOP = (size_t)SR * H;
constexpr size_t OFF_X    = 0;
constexpr size_t OFF_XR   = OFF_X   + SZ_NODE;
constexpr size_t OFF_XZ   = OFF_XR  + SZ_NODE;
constexpr size_t OFF_XH   = OFF_XZ  + SZ_NODE;
constexpr size_t OFF_XU   = OFF_XH  + SZ_NODE;
constexpr size_t OFF_H    = OFF_XU  + SZ_NODE;
constexpr size_t OFF_HU   = OFF_H   + SZ_EDGE;
constexpr size_t OFF_SUMH = OFF_HU  + SZ_EDGE;
constexpr size_t OFF_SHC  = OFF_SUMH+ SZ_EDGE;
constexpr size_t OFF_SGC  = OFF_SHC + SZ_LVL;
constexpr size_t OFF_TZ   = OFF_SGC + SZ_LVL;
constexpr size_t OFF_O    = OFF_TZ  + SZ_LVL;
constexpr size_t OFF_HS   = OFF_O   + SZ_STOP;
constexpr size_t OFF_TVU  = OFF_HS  + SZ_STOP;
constexpr size_t OFF_TVW  = OFF_TVU + (size_t)B*H;
constexpr size_t OFF_P    = OFF_TVW + (size_t)B*H;
constexpr size_t OFF_SCO  = OFF_P   + SZ_NODE;
constexpr size_t OFF_PL   = OFF_SCO + (size_t)NH*V;
constexpr size_t OFF_PC   = OFF_PL  + NH;
constexpr size_t OFF_SL   = OFF_PC  + NH;
constexpr size_t OFF_SCR  = OFF_SL  + SR;
constexpr size_t POOL_SZ  = OFF_SCR + SR;
__device__ float g_pool[POOL_SZ];

// TF32 round (to nearest) — bit pattern returned as float.
__device__ __forceinline__ float tf32r(float x) {
  uint32_t r;
  asm("cvt.rna.tf32.f32 %0, %1;" : "=r"(r) : "f"(x));
  return __uint_as_float(r);
}

// ---------------- GEMM: C = A @ W^T via tf32 tensor cores ----------------
// 128x64 block tile, 8 warps, each warp 32x32 (2 x m16 by 4 x n8 mma tiles).
// Row-major smem staging (stride BK+4=20): conflict-free fragment LDS
// (bank = (20g+t) mod 32 covers all 32 banks) and float2 STS.
#define BM 128
#define BN 64
#define BK 16
#define SKS (BK + 4)   // smem k-stride (20): conflict-free for mma frag loads

enum { EPI_STORE = 0, EPI_CELL = 1, EPI_STOP = 2, EPI_PRED = 3 };

struct GemmArgs {
  int M, N, K;
  const float* A; int lda;
  int amap_off;
  const float* W; int ldw;
  const float* bias;
  float* C; int ldc;
  int epi;
  int out_map;
  int emap_off;
  const float* Tz; const float* XZ; const float* XH;
  const float* Wzb; const float* Whb; const float* SumH; float* Hout;
  const float* XU; const float* TVu;
  const float* TVw;
};

__device__ __forceinline__ float sigmoidf_(float x) { return 1.f / (1.f + expf(-x)); }

__device__ __forceinline__ void mma_tf32(float c[4], const uint32_t a[4], const uint32_t b[2]) {
  asm volatile(
    "mma.sync.aligned.m16n8k8.row.col.f32.tf32.tf32.f32 "
    "{%0,%1,%2,%3}, {%4,%5,%6,%7}, {%8,%9}, {%0,%1,%2,%3};"
    : "+f"(c[0]), "+f"(c[1]), "+f"(c[2]), "+f"(c[3])
    : "r"(a[0]), "r"(a[1]), "r"(a[2]), "r"(a[3]), "r"(b[0]), "r"(b[1]));
}

__device__ __forceinline__ void apply_epi(const GemmArgs& a, int eblk, int r, int n, float v) {
  if (n >= a.N || r >= a.M) return;
  int b = r & 1023;
  if (a.epi == EPI_STORE) {
    if (a.bias) v += a.bias[n];
    int row = r;
    if (a.out_map) row = eblk * 1024 + b;
    a.C[(size_t)row * a.ldc + n] = v;
  } else if (a.epi == EPI_CELL) {
    int e = c_maps[a.emap_off + (r >> 10)];
    int g = e * 1024 + b;
    int xr = (b * 16 + c_src[e]) * H;
    float z   = sigmoidf_(a.Tz[(size_t)r * H + n] + a.XZ[xr + n] + a.Wzb[n]);
    float pre = tanhf(v + a.XH[xr + n] + a.Whb[n]);
    float sh  = a.SumH[(size_t)g * H + n];
    a.Hout[(size_t)g * H + n] = (1.f - z) * sh + z * pre;
  } else if (a.epi == EPI_STOP) {
    int e = r >> 10;
    int srcn = (e < 30) ? c_src[e] : 0;
    int xr = (b * 16 + srcn) * H;
    float t = v + a.XU[xr + n] + a.TVu[(size_t)b * H + n];
    a.C[(size_t)r * a.ldc + n] = fmaxf(t, 0.f);
  } else { // EPI_PRED
    float t = v + a.TVw[(size_t)b * H + n];
    a.C[(size_t)r * a.ldc + n] = fmaxf(t, 0.f);
  }
}

__global__ __launch_bounds__(256, 3) void gemm_kernel(GemmArgs a) {
  __shared__ __align__(8) float As[BM][SKS];
  __shared__ __align__(8) float Bs[BN][SKS];
  const int tn0 = blockIdx.x * BN;
  const int tm0 = blockIdx.y * BM;
  const int tid = threadIdx.x;
  const int wid = tid >> 5, lane = tid & 31;
  const int wm = wid >> 1, wn = wid & 1;      // warp grid 4 x 2
  const int g = lane >> 2, t = lane & 3;

  int eblk = -2;
  if (a.amap_off >= 0) eblk = c_maps[a.amap_off + (tm0 >> 10)];

  float acc[2][4][4];
  #pragma unroll
  for (int mt = 0; mt < 2; mt++)
    #pragma unroll
    for (int nt = 0; nt < 4; nt++)
      #pragma unroll
      for (int e = 0; e < 4; e++) acc[mt][nt][e] = 0.f;

  // A loader: 2 threads per row (0..127), 8 k each
  const int lr = tid >> 1;
  const int lk = (tid & 1) * 8;
  const float* Arow = nullptr;
  if (eblk != -1) {
    int grow = (a.amap_off >= 0) ? (eblk * 1024 + ((tm0 + lr) & 1023)) : (tm0 + lr);
    Arow = a.A + (size_t)grow * a.lda;
  }
  // B loader: 4 threads per row (0..63), 4 k each
  const int lb = tid >> 2;
  const int kb2 = (tid & 3) * 4;
  const bool nok = (tn0 + lb) < a.N;
  const float* Wrow = a.W + (size_t)(tn0 + lb) * a.ldw;

  const int K = a.K;
  float2 ar[4], br[2];
  #pragma unroll
  for (int j = 0; j < 4; j++) {
    int k = lk + 2 * j;
    ar[j] = (Arow && k + 2 <= K) ? *(const float2*)(Arow + k) : make_float2(0.f, 0.f);
  }
  #pragma unroll
  for (int j = 0; j < 2; j++) {
    int k = kb2 + 2 * j;
    br[j] = (nok && k + 2 <= K) ? *(const float2*)(Wrow + k) : make_float2(0.f, 0.f);
  }

  for (int k0 = 0; k0 < K; k0 += BK) {
    __syncthreads();
    #pragma unroll
    for (int j = 0; j < 4; j++)
      *(float2*)&As[lr][lk + 2 * j] = make_float2(tf32r(ar[j].x), tf32r(ar[j].y));
    #pragma unroll
    for (int j = 0; j < 2; j++)
      *(float2*)&Bs[lb][kb2 + 2 * j] = make_float2(tf32r(br[j].x), tf32r(br[j].y));
    __syncthreads();
    int kn = k0 + BK;
    if (kn < K) {
      #pragma unroll
      for (int j = 0; j < 4; j++) {
        int k = kn + lk + 2 * j;
        ar[j] = (Arow && k + 2 <= K) ? *(const float2*)(Arow + k) : make_float2(0.f, 0.f);
      }
      #pragma unroll
      for (int j = 0; j < 2; j++) {
        int k = kn + kb2 + 2 * j;
        br[j] = (nok && k + 2 <= K) ? *(const float2*)(Wrow + k) : make_float2(0.f, 0.f);
      }
    }
    #pragma unroll
    for (int ks = 0; ks < 2; ks++) {
      const int kb = ks * 8;
      uint32_t af[2][4], bf[4][2];
      #pragma unroll
      for (int mt = 0; mt < 2; mt++) {
        int m = wm * 32 + mt * 16;
        af[mt][0] = __float_as_uint(As[m + g][kb + t]);
        af[mt][1] = __float_as_uint(As[m + g + 8][kb + t]);
        af[mt][2] = __float_as_uint(As[m + g][kb + t + 4]);
        af[mt][3] = __float_as_uint(As[m + g + 8][kb + t + 4]);
      }
      #pragma unroll
      for (int nt = 0; nt < 4; nt++) {
        int n = wn * 32 + nt * 8;
        bf[nt][0] = __float_as_uint(Bs[n + g][kb + t]);
        bf[nt][1] = __float_as_uint(Bs[n + g][kb + t + 4]);
      }
      #pragma unroll
      for (int mt = 0; mt < 2; mt++)
        #pragma unroll
        for (int nt = 0; nt < 4; nt++)
          mma_tf32(acc[mt][nt], af[mt], bf[nt]);
    }
  }

  // epilogue: fragment (r,n) mapping — c0:(g,2t) c1:(g,2t+1) c2:(g+8,2t) c3:(g+8,2t+1)
  #pragma unroll
  for (int mt = 0; mt < 2; mt++) {
    int rb = tm0 + wm * 32 + mt * 16;
    #pragma unroll
    for (int nt = 0; nt < 4; nt++) {
      int nb = tn0 + wn * 32 + nt * 8;
      apply_epi(a, eblk, rb + g,     nb + 2 * t,     acc[mt][nt][0]);
      apply_epi(a, eblk, rb + g,     nb + 2 * t + 1, acc[mt][nt][1]);
      apply_epi(a, eblk, rb + g + 8, nb + 2 * t,     acc[mt][nt][2]);
      apply_epi(a, eblk, rb + g + 8, nb + 2 * t + 1, acc[mt][nt][3]);
    }
  }
}

// ---------------- elementwise / reduce kernels ----------------
__global__ void embed_kernel(float* X, const int* wid, const float* emb) {
  int n = blockIdx.x;
  const float* src = emb + (size_t)wid[n] * H;
  float* dst = X + (size_t)n * H;
  for (int j = threadIdx.x; j < H; j += blockDim.x) dst[j] = src[j];
}

__global__ void gather_cell_kernel(int lvl_off, const float* __restrict__ Urb,
                                   const float* __restrict__ XR,
                                   const float* __restrict__ h,
                                   const float* __restrict__ hU,
                                   float* SumH, float* SHc, float* SGc) {
  int r = blockIdx.x;
  int idx = r >> 10, b = r & 1023;
  int e = c_maps[lvl_off + idx];
  int p0 = c_pred0[e], p1 = c_pred1[e];
  const float* xr = XR + (size_t)(b * 16 + c_src[e]) * H;
  size_t go = (size_t)(e * 1024 + b) * H;
  size_t ro = (size_t)r * H;
  for (int j = threadIdx.x; j < H; j += blockDim.x) {
    float sh = 0.f, sg = 0.f;
    if (p0 >= 0) {
      size_t q = (size_t)(p0 * 1024 + b) * H + j;
      float hv = h[q];
      float rr = sigmoidf_(xr[j] + hU[q] + Urb[j]);
      sh += hv; sg += rr * hv;
    }
    if (p1 >= 0) {
      size_t q = (size_t)(p1 * 1024 + b) * H + j;
      float hv = h[q];
      float rr = sigmoidf_(xr[j] + hU[q] + Urb[j]);
      sh += hv; sg += rr * hv;
    }
    SumH[go + j] = sh;
    SHc[ro + j] = sh;
    SGc[ro + j] = sg;
  }
}

__global__ void build_o_kernel(const float* __restrict__ SumH,
                               const float* __restrict__ h, float* O) {
  int r = blockIdx.x;
  size_t off = (size_t)r * H;
  if (r < ER) {
    int e = r >> 10, b = r & 1023;
    if (e & 1) {
      size_t rev = (size_t)((e ^ 1) * 1024 + b) * H;
      for (int j = threadIdx.x; j < H; j += blockDim.x) O[off + j] = SumH[off + j] + h[rev + j];
    } else {
      for (int j = threadIdx.x; j < H; j += blockDim.x) O[off + j] = SumH[off + j];
    }
  } else {
    int b = r - ER;
    size_t r1 = (size_t)(1 * 1024 + b) * H, r3 = (size_t)(3 * 1024 + b) * H;
    for (int j = threadIdx.x; j < H; j += blockDim.x) O[off + j] = h[r1 + j] + h[r3 + j];
  }
}

__global__ void stop_reduce_kernel(const float* __restrict__ Hs,
                                   const float* __restrict__ Usw, const float* __restrict__ Usb,
                                   float* SL, float* SC) {
  __shared__ double red[256];
  int r = blockIdx.x;
  const float* hs = Hs + (size_t)r * H;
  double p = 0.0;
  for (int j = threadIdx.x; j < H; j += 256) p = fma((double)hs[j], (double)Usw[j], p);
  red[threadIdx.x] = p; __syncthreads();
  for (int s = 128; s > 0; s >>= 1) {
    if (threadIdx.x < s) red[threadIdx.x] += red[threadIdx.x + s];
    __syncthreads();
  }
  if (threadIdx.x == 0) {
    double s = red[0] + (double)Usb[0];
    double st = (r < ER) ? (((r >> 10) & 1) ? 0.0 : 1.0) : 0.0;
    double sp = (s > 0.0 ? s : 0.0) + log1p(exp(-fabs(s)));
    SL[r] = (float)(sp - s * st);
    double pr = (s >= 0.0) ? 1.0 : 0.0;
    SC[r] = (pr == st) ? 1.f : 0.f;
  }
}

__global__ void pred_ce_kernel(const float* __restrict__ scores, const int* __restrict__ wid,
                               float* PL, float* PC) {
  __shared__ float smax[256]; __shared__ int sidx[256]; __shared__ double ssum[256];
  int r = blockIdx.x;
  const float* sc = scores + (size_t)r * V;
  float m = -1e30f; int mi = 0x7fffffff;
  for (int v = threadIdx.x; v < V; v += 256) {
    float x = sc[v];
    if (x > m) { m = x; mi = v; }
  }
  smax[threadIdx.x] = m; sidx[threadIdx.x] = mi; __syncthreads();
  for (int s = 128; s > 0; s >>= 1) {
    if (threadIdx.x < s) {
      float om = smax[threadIdx.x + s]; int oi = sidx[threadIdx.x + s];
      if (om > smax[threadIdx.x] || (om == smax[threadIdx.x] && oi < sidx[threadIdx.x])) {
        smax[threadIdx.x] = om; sidx[threadIdx.x] = oi;
      }
    }
    __syncthreads();
  }
  float mx = smax[0]; int amax = sidx[0];
  double p = 0.0;
  for (int v = threadIdx.x; v < V; v += 256) p += (double)expf(sc[v] - mx);
  ssum[threadIdx.x] = p; __syncthreads();
  for (int s = 128; s > 0; s >>= 1) {
    if (threadIdx.x < s) ssum[threadIdx.x] += ssum[threadIdx.x + s];
    __syncthreads();
  }
  if (threadIdx.x == 0) {
    double lse = (double)mx + log(ssum[0]);
    int k = r >> 10, b = r & 1023;
    int t = wid[b * 16 + k];
    PL[r] = (float)(lse - (double)sc[t]);
    PC[r] = (amax == t) ? 1.f : 0.f;
  }
}

__global__ void finalize_kernel(const float* PL, const float* PC,
                                const float* SL, const float* SC,
                                float* out, int out_size) {
  __shared__ double s0[256], s1[256], s2[256], s3[256];
  int tid = threadIdx.x;
  double pl = 0, pc = 0, sl = 0, sc = 0;
  for (int r = tid; r < NH; r += 256) { pl += PL[r]; pc += PC[r]; }
  for (int r = tid; r < SR; r += 256) { sl += SL[r]; sc += SC[r]; }
  s0[tid] = pl; s1[tid] = sl; s2[tid] = pc; s3[tid] = sc;
  __syncthreads();
  for (int s = 128; s > 0; s >>= 1) {
    if (tid < s) { s0[tid] += s0[tid + s]; s1[tid] += s1[tid + s]; s2[tid] += s2[tid + s]; s3[tid] += s3[tid + s]; }
    __syncthreads();
  }
  if (tid == 0) {
    float vals[4] = { (float)(s0[0] / 1024.0), (float)(s1[0] / 1024.0),
                      (float)(s2[0] / 16384.0), (float)(s3[0] / 31744.0) };
    for (int i = 0; i < 4 && i < out_size; i++) out[i] = vals[i];
  }
}

// ---------------- host orchestration ----------------
static GemmArgs mk(int M, int N, int K, const float* A, int lda, int amap,
                   const float* W, int ldw, const float* bias,
                   float* C, int ldc, int epi, int omap, int emap) {
  GemmArgs a = {};
  a.M = M; a.N = N; a.K = K; a.A = A; a.lda = lda; a.amap_off = amap;
  a.W = W; a.ldw = ldw; a.bias = bias; a.C = C; a.ldc = ldc;
  a.epi = epi; a.out_map = omap; a.emap_off = emap;
  return a;
}
static void run(const GemmArgs& a) {
  dim3 grid((a.N + BN - 1) / BN, (a.M + BM - 1) / BM);
  gemm_kernel<<<grid, 256>>>(a);
}

extern "C" void kernel_launch(void* const* d_in, const int* in_sizes, int n_in,
                              void* d_out, int out_size) {
  const int*   wid      = (const int*)  d_in[0];
  const float* tree_vec = (const float*)d_in[1];
  const float* emb      = (const float*)d_in[2];
  const float* W_r      = (const float*)d_in[3];
  const float* U_r_w    = (const float*)d_in[4];
  const float* U_r_b    = (const float*)d_in[5];
  const float* W_z_w    = (const float*)d_in[6];
  const float* W_z_b    = (const float*)d_in[7];
  const float* W_h_w    = (const float*)d_in[8];
  const float* W_h_b    = (const float*)d_in[9];
  const float* W_w      = (const float*)d_in[10];
  const float* W_b      = (const float*)d_in[11];
  const float* U_w      = (const float*)d_in[12];
  const float* U_b      = (const float*)d_in[13];
  const float* W_o_w    = (const float*)d_in[14];
  const float* W_o_b    = (const float*)d_in[15];
  const float* U_s_w    = (const float*)d_in[16];
  const float* U_s_b    = (const float*)d_in[17];

  float* pool = nullptr;
  cudaGetSymbolAddress((void**)&pool, g_pool);
  float* X    = pool + OFF_X;
  float* XR   = pool + OFF_XR;
  float* XZ   = pool + OFF_XZ;
  float* XH   = pool + OFF_XH;
  float* XU   = pool + OFF_XU;
  float* h    = pool + OFF_H;
  float* hU   = pool + OFF_HU;
  float* SumH = pool + OFF_SUMH;
  float* SHc  = pool + OFF_SHC;
  float* SGc  = pool + OFF_SGC;
  float* Tz   = pool + OFF_TZ;
  float* O    = pool + OFF_O;
  float* Hs   = pool + OFF_HS;
  float* TVu  = pool + OFF_TVU;
  float* TVw  = pool + OFF_TVW;
  float* P    = pool + OFF_P;
  float* SCO  = pool + OFF_SCO;
  float* PL   = pool + OFF_PL;
  float* PC   = pool + OFF_PC;
  float* SL   = pool + OFF_SL;
  float* SCR  = pool + OFF_SCR;

  // 1) node embeddings + per-node precomputes
  embed_kernel<<<NH, 256>>>(X, wid, emb);
  run(mk(NH, H, H, X, H, -1, W_r,   H,     nullptr, XR, H, EPI_STORE, 0, -1));
  run(mk(NH, H, H, X, H, -1, W_z_w, 2 * H, nullptr, XZ, H, EPI_STORE, 0, -1));
  run(mk(NH, H, H, X, H, -1, W_h_w, 2 * H, nullptr, XH, H, EPI_STORE, 0, -1));
  run(mk(NH, H, H, X, H, -1, U_w,   956,   nullptr, XU, H, EPI_STORE, 0, -1));
  run(mk(B, H, 56, tree_vec, 56, -1, U_w + 2 * H, 956, U_b, TVu, H, EPI_STORE, 0, -1));
  run(mk(B, H, 56, tree_vec, 56, -1, W_w + H,     506, W_b, TVw, H, EPI_STORE, 0, -1));

  // 2) 7-level recurrence over the DFS-time dependency DAG
  const int LVL_OFF[8] = {0, 9, 14, 18, 21, 24, 26, 30};
  const int HUL_OFF[8] = {0, 9, 14, 16, 18, 19, 21, 21};
  for (int l = 0; l < 7; l++) {
    int ne = LVL_OFF[l + 1] - LVL_OFF[l];
    int rows = ne * 1024;
    gather_cell_kernel<<<rows, 256>>>(LVL_OFF[l], U_r_b, XR, h, hU, SumH, SHc, SGc);
    run(mk(rows, H, H, SHc, H, -1, W_z_w + H, 2 * H, nullptr, Tz, H, EPI_STORE, 0, -1));
    GemmArgs a2 = mk(rows, H, H, SGc, H, -1, W_h_w + H, 2 * H, nullptr, nullptr, 0,
                     EPI_CELL, 0, LVL_OFF[l]);
    a2.Tz = Tz; a2.XZ = XZ; a2.XH = XH; a2.Wzb = W_z_b; a2.Whb = W_h_b;
    a2.SumH = SumH; a2.Hout = h;
    run(a2);
    int nhu = HUL_OFF[l + 1] - HUL_OFF[l];
    if (nhu > 0)
      run(mk(nhu * 1024, H, H, h, H, 30 + HUL_OFF[l], U_r_w, H, nullptr, hU, H, EPI_STORE, 1, -1));
  }

  // 3) stop head
  build_o_kernel<<<SR, 256>>>(SumH, h, O);
  GemmArgs as = mk(SR, H, H, O, H, -1, U_w + H, 956, nullptr, Hs, H, EPI_STOP, 0, -1);
  as.XU = XU; as.TVu = TVu;
  run(as);
  stop_reduce_kernel<<<SR, 256>>>(Hs, U_s_w, U_s_b, SL, SCR);

  // 4) word-prediction head
  GemmArgs ap = mk(NH, H, H, h, H, 51, W_w, 506, nullptr, P, H, EPI_PRED, 0, -1);
  ap.TVw = TVw;
  run(ap);
  run(mk(NH, V, H, P, H, -1, W_o_w, H, W_o_b, SCO, V, EPI_STORE, 0, -1));
  pred_ce_kernel<<<NH, 256>>>(SCO, wid, PL, PC);

  // 5) deterministic final reduction
  finalize_kernel<<<1, 256>>>(PL, PC, SL, SCR, (float*)d_out, out_size);
}